// round 10
// baseline (speedup 1.0000x reference)
#include <cuda_runtime.h>

#define N_TRIALS   8
#define T_MS       2500
#define N_NEURONS  16000
#define N_SAMPLES  50
#define K_MAX      160
#define N_BINS     20
#define SYNC_COST  10.0f
#define EPS_F      1e-7f
#define U_MAX      8000     // per-trial union cap (sum of all counts <= 8000)
#define TCHUNK     10       // timesteps per fused block
#define CHUNK      2048     // smem staging capacity (fast path if len <= CHUNK)
#define NBGRP      4        // fano bin groups
#define BINS_PER_GRP (N_BINS / NBGRP)

// round(logspace(-3,0,20)*1000), matching numpy exactly
__constant__ int c_bins[N_BINS] = {1,1,2,3,4,6,9,13,18,26,38,55,78,113,162,234,336,483,695,1000};

// scratch (no allocations allowed -> __device__ globals)
__device__ int   g_U[N_TRIALS * U_MAX];      // per-trial sorted union (neuron ids)
__device__ int   g_lenU[N_TRIALS];
__device__ int   g_slist[N_TRIALS * 64];     // sample ids per trial
__device__ int   g_scount[N_TRIALS];
__device__ int   g_P[N_SAMPLES * K_MAX];     // per-sample position in its trial union
__device__ float g_sel[N_SAMPLES * T_MS];
__device__ float g_fano_parts[N_BINS * N_SAMPLES];

__device__ __forceinline__ void cp_async4(void* smem_dst, const void* gmem_src)
{
    unsigned sa = (unsigned)__cvta_generic_to_shared(smem_dst);
    asm volatile("cp.async.ca.shared.global [%0], [%1], 4;\n" :: "r"(sa), "l"(gmem_src));
}
__device__ __forceinline__ void cp_commit()  { asm volatile("cp.async.commit_group;\n"); }
__device__ __forceinline__ void cp_wait0()   { asm volatile("cp.async.wait_group 0;\n"); }
__device__ __forceinline__ void cp_wait1()   { asm volatile("cp.async.wait_group 1;\n"); }

// ---------------------------------------------------------------------------
// Kernel A: per trial r, sorted union + per-sample positions + sample list.
// One block per trial; deterministic flag + block scan, no atomics.
// ---------------------------------------------------------------------------
__global__ void __launch_bounds__(512) prep_kernel(const int* __restrict__ trials,
                                                   const int* __restrict__ idx,
                                                   const int* __restrict__ counts)
{
    const int r   = blockIdx.x;
    const int tid = threadIdx.x;

    __shared__ short sm[N_NEURONS];   // flag, then position map (32 KB)
    __shared__ int   bsum[512];
    __shared__ int   slist_s[52];
    __shared__ int   scount_s;

    for (int n = tid; n < N_NEURONS; n += 512) sm[n] = 0;
    if (tid == 0) {
        int c = 0;
        for (int s = 0; s < N_SAMPLES; s++)
            if (trials[s] == r) slist_s[c++] = s;
        scount_s = c;
    }
    __syncthreads();

    const int sc = scount_s;

    for (int p = tid; p < sc * K_MAX; p += 512) {
        const int si = p / K_MAX, k = p % K_MAX;
        const int s  = slist_s[si];
        if (k < counts[s]) sm[idx[s * K_MAX + k]] = 1;
    }
    __syncthreads();

    const int base = tid * 32;   // 512*32 = 16384 >= 16000
    int loc = 0;
    #pragma unroll
    for (int i = 0; i < 32; i++) {
        const int n = base + i;
        if (n < N_NEURONS) loc += sm[n];
    }
    bsum[tid] = loc;
    __syncthreads();

    for (int off = 1; off < 512; off <<= 1) {
        const int v   = bsum[tid];
        const int add = (tid >= off) ? bsum[tid - off] : 0;
        __syncthreads();
        bsum[tid] = v + add;
        __syncthreads();
    }
    const int excl = (tid == 0) ? 0 : bsum[tid - 1];

    int pos = excl;
    #pragma unroll
    for (int i = 0; i < 32; i++) {
        const int n = base + i;
        if (n < N_NEURONS) {
            const short f = sm[n];
            sm[n] = (short)pos;
            if (f) { g_U[r * U_MAX + pos] = n; pos++; }
        }
    }
    __syncthreads();

    if (tid == 511) g_lenU[r] = pos;
    if (tid == 0)   g_scount[r] = sc;
    if (tid < sc)   g_slist[r * 64 + tid] = slist_s[tid];

    for (int p = tid; p < sc * K_MAX; p += 512) {
        const int si = p / K_MAX, k = p % K_MAX;
        const int s  = slist_s[si];
        if (k < counts[s])
            g_P[s * K_MAX + k] = (int)sm[idx[s * K_MAX + k]];
    }
}

// ---------------------------------------------------------------------------
// Kernel B (fused): one block per (trial, 10 consecutive t).
// Fast path (union <= CHUNK): cp.async double-buffered — the NEXT timestep's
// ~430 scattered loads are in flight across the barrier while warps consume
// the current buffer, so the DRAM stream never idles.
// Each DRAM line fetched exactly once per (r,t); no intermediate global buffer.
// ---------------------------------------------------------------------------
__global__ void __launch_bounds__(256) fused_kernel(const float* __restrict__ spikes,
                                                    const int*   __restrict__ counts)
{
    const int r   = blockIdx.y;
    const int t0  = blockIdx.x * TCHUNK;
    const int tid = threadIdx.x;

    __shared__ float buf[2][CHUNK];   // 16 KB
    __shared__ int   sU[CHUNK];       // 8 KB (fast path)
    __shared__ float accv[64];        // fallback accumulators

    const int len = g_lenU[r];
    const int sc  = g_scount[r];
    if (sc == 0) return;

    const float* __restrict__ base = spikes + (long long)r * T_MS * N_NEURONS;
    const int wid  = tid >> 5;
    const int lane = tid & 31;

    if (len <= CHUNK) {
        for (int j = tid; j < len; j += 256) sU[j] = g_U[r * U_MAX + j];
        __syncthreads();

        // prologue: prefetch t0 into buf[0]
        {
            const float* __restrict__ rowp = base + (long long)t0 * N_NEURONS;
            for (int j = tid; j < len; j += 256)
                cp_async4(&buf[0][j], rowp + sU[j]);
            cp_commit();
        }

        #pragma unroll 1
        for (int ti = 0; ti < TCHUNK; ti++) {
            const int t   = t0 + ti;
            const int cur = ti & 1;

            if (ti + 1 < TCHUNK) {
                // issue next timestep BEFORE waiting on current
                const float* __restrict__ rowp = base + (long long)(t + 1) * N_NEURONS;
                for (int j = tid; j < len; j += 256)
                    cp_async4(&buf[cur ^ 1][j], rowp + sU[j]);
                cp_commit();
                cp_wait1();          // current buffer complete; next still in flight
            } else {
                cp_wait0();
            }
            __syncthreads();

            // consume current buffer: warps sweep this trial's samples
            for (int si = wid; si < sc; si += 8) {
                const int s   = g_slist[r * 64 + si];
                const int cnt = counts[s];
                const int* __restrict__ Ps = g_P + s * K_MAX;

                float v = 0.f;
                for (int k = lane; k < cnt; k += 32)
                    v += buf[cur][Ps[k]];

                #pragma unroll
                for (int o = 16; o > 0; o >>= 1)
                    v += __shfl_down_sync(0xFFFFFFFFu, v, o);

                if (lane == 0) g_sel[s * T_MS + t] = v;   // exact small integer
            }
            __syncthreads();   // buf[cur] free for reuse at iter ti+2's issue
        }
    } else {
        // Safety fallback (len > CHUNK): piece-wise staged, non-pipelined.
        #pragma unroll 1
        for (int ti = 0; ti < TCHUNK; ti++) {
            const int t = t0 + ti;
            for (int i = tid; i < 64; i += 256) accv[i] = 0.f;
            __syncthreads();

            for (int c0 = 0; c0 < len; c0 += CHUNK) {
                const int clen = (len - c0 < CHUNK) ? (len - c0) : CHUNK;
                const float* __restrict__ rowp = base + (long long)t * N_NEURONS;
                for (int j = tid; j < clen; j += 256)
                    buf[0][j] = rowp[g_U[r * U_MAX + c0 + j]];
                __syncthreads();

                for (int si = wid; si < sc; si += 8) {
                    const int s   = g_slist[r * 64 + si];
                    const int cnt = counts[s];
                    const int* __restrict__ Ps = g_P + s * K_MAX;
                    float v = 0.f;
                    for (int k = lane; k < cnt; k += 32) {
                        const int p = Ps[k];
                        if (p >= c0 && p < c0 + clen) v += buf[0][p - c0];
                    }
                    #pragma unroll
                    for (int o = 16; o > 0; o >>= 1)
                        v += __shfl_down_sync(0xFFFFFFFFu, v, o);
                    if (lane == 0) accv[si] += v;
                }
                __syncthreads();
            }
            for (int si = tid; si < sc; si += 256)
                g_sel[g_slist[r * 64 + si] * T_MS + t] = accv[si];
            __syncthreads();
        }
    }
}

// ---------------------------------------------------------------------------
// Kernel C: fano, split over NBGRP bin groups per sample (shorter barrier
// chains). grid (N_SAMPLES, NBGRP). Two-pass variance, deterministic.
// ---------------------------------------------------------------------------
__global__ void __launch_bounds__(256) fano_kernel()
{
    const int s   = blockIdx.x;
    const int bg  = blockIdx.y;
    const int tid = threadIdx.x;

    __shared__ float row[T_MS];
    __shared__ float binsum[T_MS];
    __shared__ float red[256];

    for (int t = tid; t < T_MS; t += blockDim.x)
        row[t] = g_sel[s * T_MS + t];
    __syncthreads();

    for (int bi = 0; bi < BINS_PER_GRP; bi++) {
        const int b  = bg * BINS_PER_GRP + bi;
        const int bs = c_bins[b];
        const int nb = T_MS / bs;

        for (int j = tid; j < nb; j += blockDim.x) {
            const int base = j * bs;
            float b0=0.f, b1=0.f, b2=0.f, b3=0.f;
            int i = 0;
            for (; i + 4 <= bs; i += 4) {
                b0 += row[base + i + 0];
                b1 += row[base + i + 1];
                b2 += row[base + i + 2];
                b3 += row[base + i + 3];
            }
            float acc = (b0+b1)+(b2+b3);
            for (; i < bs; i++) acc += row[base + i];
            binsum[j] = acc;
        }
        __syncthreads();

        float part = 0.f;
        for (int j = tid; j < nb; j += blockDim.x) part += binsum[j];
        red[tid] = part;
        __syncthreads();
        #pragma unroll
        for (int off = 128; off > 0; off >>= 1) {
            if (tid < off) red[tid] += red[tid + off];
            __syncthreads();
        }
        const float mean = red[0] / (float)nb;
        __syncthreads();

        float part2 = 0.f;
        for (int j = tid; j < nb; j += blockDim.x) {
            const float d = binsum[j] - mean;
            part2 += d * d;
        }
        red[tid] = part2;
        __syncthreads();
        #pragma unroll
        for (int off = 128; off > 0; off >>= 1) {
            if (tid < off) red[tid] += red[tid + off];
            __syncthreads();
        }
        if (tid == 0) {
            const float var = red[0] / (float)nb;
            g_fano_parts[b * N_SAMPLES + s] = var / fmaxf(mean, EPS_F);
        }
        __syncthreads();
    }
}

// ---------------------------------------------------------------------------
// Kernel D: parallel loss. 20 warps, warp b reduces its 50 sample fanos.
// ---------------------------------------------------------------------------
__global__ void __launch_bounds__(640) loss_kernel(const float* __restrict__ exp_fanos,
                                                   float* __restrict__ out)
{
    const int w    = threadIdx.x >> 5;
    const int lane = threadIdx.x & 31;

    __shared__ float sq[N_BINS];

    float v = 0.f;
    if (lane < N_SAMPLES)      v += g_fano_parts[w * N_SAMPLES + lane];
    if (lane + 32 < N_SAMPLES) v += g_fano_parts[w * N_SAMPLES + lane + 32];
    #pragma unroll
    for (int off = 16; off > 0; off >>= 1)
        v += __shfl_down_sync(0xFFFFFFFFu, v, off);
    if (lane == 0) {
        const float fano = v / (float)N_SAMPLES;
        const float d = exp_fanos[w] - fano;
        sq[w] = d * d;
    }
    __syncthreads();

    if (w == 0) {
        float x = (lane < N_BINS) ? sq[lane] : 0.f;
        #pragma unroll
        for (int off = 16; off > 0; off >>= 1)
            x += __shfl_down_sync(0xFFFFFFFFu, x, off);
        if (lane == 0) out[0] = SYNC_COST * (x / (float)N_BINS);
    }
}

// ---------------------------------------------------------------------------
extern "C" void kernel_launch(void* const* d_in, const int* in_sizes, int n_in,
                              void* d_out, int out_size)
{
    const float* spikes    = (const float*)d_in[0];
    const float* exp_fanos = (const float*)d_in[1];
    const int*   trials    = (const int*)  d_in[2];
    const int*   idx       = (const int*)  d_in[3];
    const int*   counts    = (const int*)  d_in[4];
    float*       out       = (float*)d_out;

    prep_kernel<<<N_TRIALS, 512>>>(trials, idx, counts);

    dim3 gB(T_MS / TCHUNK, N_TRIALS);          // (250, 8)
    fused_kernel<<<gB, 256>>>(spikes, counts);

    dim3 gC(N_SAMPLES, NBGRP);
    fano_kernel<<<gC, 256>>>();

    loss_kernel<<<1, 640>>>(exp_fanos, out);
}

// round 12
// speedup vs baseline: 1.6129x; 1.6129x over previous
#include <cuda_runtime.h>
#include <stdint.h>

#define N_TRIALS   8
#define T_MS       2500
#define N_NEURONS  16000
#define N_SAMPLES  50
#define K_MAX      160
#define N_BINS     20
#define SYNC_COST  10.0f
#define EPS_F      1e-7f
#define SORT_N     256
#define NC         8            // neuron-space chunks (2000 neurons each)
#define MAXS       24           // max samples per trial (headroom over E[6.25])
#define TB         32           // t per block
#define NBGRP      4
#define BINS_PER_GRP (N_BINS / NBGRP)

// round(logspace(-3,0,20)*1000), matching numpy exactly
__constant__ int c_bins[N_BINS] = {1,1,2,3,4,6,9,13,18,26,38,55,78,113,162,234,336,483,695,1000};

// scratch (no allocations allowed -> __device__ globals)
__device__ int   g_sidx[N_SAMPLES * K_MAX];        // per-sample ASCENDING active indices
__device__ int   g_soff[N_SAMPLES * (NC + 1)];     // per-sample chunk offsets into sorted list
__device__ int   g_slist[N_TRIALS * MAXS];         // sample ids per trial
__device__ int   g_scount[N_TRIALS];
__device__ float g_sel[N_SAMPLES * T_MS];
__device__ float g_fano_parts[N_BINS * N_SAMPLES];

// ---------------------------------------------------------------------------
// Kernel 0a: trial -> sample-list map (1 tiny block, deterministic).
// ---------------------------------------------------------------------------
__global__ void trial_map_kernel(const int* __restrict__ trials)
{
    if (threadIdx.x == 0) {
        int cnt[N_TRIALS];
        for (int r = 0; r < N_TRIALS; r++) cnt[r] = 0;
        for (int s = 0; s < N_SAMPLES; s++) {
            const int r = trials[s];
            g_slist[r * MAXS + cnt[r]] = s;
            cnt[r]++;
        }
        for (int r = 0; r < N_TRIALS; r++) g_scount[r] = cnt[r];
    }
}

// ---------------------------------------------------------------------------
// Kernel 0b: per sample, bitonic sort its cnt active indices ascending
// (exact: 0/1 summands are order-independent), then chunk offsets by
// binary search at neuron thresholds c*2000.
// ---------------------------------------------------------------------------
__global__ void __launch_bounds__(SORT_N) sort_prep_kernel(const int* __restrict__ idx,
                                                           const int* __restrict__ counts)
{
    const int s   = blockIdx.x;
    const int tid = threadIdx.x;
    const int cnt = counts[s];

    __shared__ int a[SORT_N];
    a[tid] = (tid < cnt) ? idx[s * K_MAX + tid] : 0x7FFFFFFF;
    __syncthreads();

    for (int k = 2; k <= SORT_N; k <<= 1) {
        for (int j = k >> 1; j > 0; j >>= 1) {
            const int ixj = tid ^ j;
            if (ixj > tid) {
                const bool up = ((tid & k) == 0);
                const int x = a[tid], y = a[ixj];
                if ((x > y) == up) { a[tid] = y; a[ixj] = x; }
            }
            __syncthreads();
        }
    }

    if (tid < K_MAX)
        g_sidx[s * K_MAX + tid] = (tid < cnt) ? a[tid] : 0;

    // chunk offsets: lower_bound(a[0..cnt), c * (N_NEURONS/NC))
    if (tid <= NC) {
        const int thr = tid * (N_NEURONS / NC);
        int lo = 0, hi = cnt;
        while (lo < hi) {
            const int mid = (lo + hi) >> 1;
            if (a[mid] < thr) lo = mid + 1; else hi = mid;
        }
        g_soff[s * (NC + 1) + tid] = lo;
    }
}

// ---------------------------------------------------------------------------
// Kernel 1: sel. Block = (trial r, 32 consecutive t) x 8 warp-slots.
// Warp w handles samples si = w, w+8, w+16 of the trial; lane = t.
// k-loop split into NC neuron-space chunks with a per-chunk barrier, so every
// warp of the block touches the same 2000-neuron window simultaneously ->
// each 128B line fetched from DRAM once per (r, t-chunk) instead of once per
// sample. Hot loop is R4's proven barrier-free unrolled LDG shape.
// ---------------------------------------------------------------------------
__global__ void __launch_bounds__(256) sel_kernel(const float* __restrict__ spikes,
                                                  const int*   __restrict__ counts)
{
    const int r   = blockIdx.y;
    const int t0  = blockIdx.x * TB;
    const int tid = threadIdx.x;
    const int lane = tid & 31;
    const int w    = tid >> 5;

    __shared__ uint16_t lists[MAXS][K_MAX];   // 7.7 KB
    __shared__ int      soff_s[MAXS][NC + 1];
    __shared__ int      sids[MAXS];
    __shared__ int      sc_s;

    if (tid == 0) sc_s = g_scount[r];
    __syncthreads();
    const int sc = sc_s;
    if (sc == 0) return;

    for (int i = tid; i < sc; i += 256) sids[i] = g_slist[r * MAXS + i];
    __syncthreads();

    for (int p = tid; p < sc * K_MAX; p += 256) {
        const int si = p / K_MAX, k = p % K_MAX;
        lists[si][k] = (uint16_t)g_sidx[sids[si] * K_MAX + k];
    }
    for (int p = tid; p < sc * (NC + 1); p += 256) {
        const int si = p / (NC + 1), c = p % (NC + 1);
        soff_s[si][c] = g_soff[sids[si] * (NC + 1) + c];
    }
    __syncthreads();

    const int  t      = t0 + lane;
    const bool active = (t < T_MS);
    const float* __restrict__ row =
        spikes + ((long long)r * T_MS + t) * (long long)N_NEURONS;

    float acc0 = 0.f, acc1 = 0.f, acc2 = 0.f;

    #pragma unroll 1
    for (int c = 0; c < NC; c++) {
        if (active) {
            // slot 0
            {
                const int si = w;
                if (si < sc) {
                    const uint16_t* __restrict__ L = &lists[si][0];
                    int j = soff_s[si][c];
                    const int j1 = soff_s[si][c + 1];
                    float b0=0.f,b1=0.f,b2=0.f,b3=0.f;
                    for (; j + 4 <= j1; j += 4) {
                        b0 += row[L[j+0]]; b1 += row[L[j+1]];
                        b2 += row[L[j+2]]; b3 += row[L[j+3]];
                    }
                    float x = (b0+b1)+(b2+b3);
                    for (; j < j1; j++) x += row[L[j]];
                    acc0 += x;
                }
            }
            // slot 1
            {
                const int si = w + 8;
                if (si < sc) {
                    const uint16_t* __restrict__ L = &lists[si][0];
                    int j = soff_s[si][c];
                    const int j1 = soff_s[si][c + 1];
                    float b0=0.f,b1=0.f,b2=0.f,b3=0.f;
                    for (; j + 4 <= j1; j += 4) {
                        b0 += row[L[j+0]]; b1 += row[L[j+1]];
                        b2 += row[L[j+2]]; b3 += row[L[j+3]];
                    }
                    float x = (b0+b1)+(b2+b3);
                    for (; j < j1; j++) x += row[L[j]];
                    acc1 += x;
                }
            }
            // slot 2
            {
                const int si = w + 16;
                if (si < sc) {
                    const uint16_t* __restrict__ L = &lists[si][0];
                    int j = soff_s[si][c];
                    const int j1 = soff_s[si][c + 1];
                    float b0=0.f,b1=0.f,b2=0.f,b3=0.f;
                    for (; j + 4 <= j1; j += 4) {
                        b0 += row[L[j+0]]; b1 += row[L[j+1]];
                        b2 += row[L[j+2]]; b3 += row[L[j+3]];
                    }
                    float x = (b0+b1)+(b2+b3);
                    for (; j < j1; j++) x += row[L[j]];
                    acc2 += x;
                }
            }
        }
        __syncthreads();   // lockstep: all warps stay in the same neuron window
    }

    if (active) {
        if (w      < sc) g_sel[sids[w     ] * T_MS + t] = acc0;   // exact ints
        if (w + 8  < sc) g_sel[sids[w + 8 ] * T_MS + t] = acc1;
        if (w + 16 < sc) g_sel[sids[w + 16] * T_MS + t] = acc2;
    }
}

// ---------------------------------------------------------------------------
// Kernel 2: fano, grid (N_SAMPLES, NBGRP), 5 bins per block.
// Two-pass variance, deterministic tree reductions.
// ---------------------------------------------------------------------------
__global__ void __launch_bounds__(256) fano_kernel()
{
    const int s   = blockIdx.x;
    const int bg  = blockIdx.y;
    const int tid = threadIdx.x;

    __shared__ float row[T_MS];
    __shared__ float binsum[T_MS];
    __shared__ float red[256];

    for (int t = tid; t < T_MS; t += blockDim.x)
        row[t] = g_sel[s * T_MS + t];
    __syncthreads();

    for (int bi = 0; bi < BINS_PER_GRP; bi++) {
        const int b  = bg * BINS_PER_GRP + bi;
        const int bs = c_bins[b];
        const int nb = T_MS / bs;

        for (int j = tid; j < nb; j += blockDim.x) {
            const int base = j * bs;
            float b0=0.f, b1=0.f, b2=0.f, b3=0.f;
            int i = 0;
            for (; i + 4 <= bs; i += 4) {
                b0 += row[base + i + 0];
                b1 += row[base + i + 1];
                b2 += row[base + i + 2];
                b3 += row[base + i + 3];
            }
            float acc = (b0+b1)+(b2+b3);
            for (; i < bs; i++) acc += row[base + i];
            binsum[j] = acc;
        }
        __syncthreads();

        float part = 0.f;
        for (int j = tid; j < nb; j += blockDim.x) part += binsum[j];
        red[tid] = part;
        __syncthreads();
        #pragma unroll
        for (int off = 128; off > 0; off >>= 1) {
            if (tid < off) red[tid] += red[tid + off];
            __syncthreads();
        }
        const float mean = red[0] / (float)nb;
        __syncthreads();

        float part2 = 0.f;
        for (int j = tid; j < nb; j += blockDim.x) {
            const float d = binsum[j] - mean;
            part2 += d * d;
        }
        red[tid] = part2;
        __syncthreads();
        #pragma unroll
        for (int off = 128; off > 0; off >>= 1) {
            if (tid < off) red[tid] += red[tid + off];
            __syncthreads();
        }
        if (tid == 0) {
            const float var = red[0] / (float)nb;
            g_fano_parts[b * N_SAMPLES + s] = var / fmaxf(mean, EPS_F);
        }
        __syncthreads();
    }
}

// ---------------------------------------------------------------------------
// Kernel 3: parallel loss. 20 warps, warp b reduces its 50 sample fanos.
// ---------------------------------------------------------------------------
__global__ void __launch_bounds__(640) loss_kernel(const float* __restrict__ exp_fanos,
                                                   float* __restrict__ out)
{
    const int w    = threadIdx.x >> 5;
    const int lane = threadIdx.x & 31;

    __shared__ float sq[N_BINS];

    float v = 0.f;
    if (lane < N_SAMPLES)      v += g_fano_parts[w * N_SAMPLES + lane];
    if (lane + 32 < N_SAMPLES) v += g_fano_parts[w * N_SAMPLES + lane + 32];
    #pragma unroll
    for (int off = 16; off > 0; off >>= 1)
        v += __shfl_down_sync(0xFFFFFFFFu, v, off);
    if (lane == 0) {
        const float fano = v / (float)N_SAMPLES;
        const float d = exp_fanos[w] - fano;
        sq[w] = d * d;
    }
    __syncthreads();

    if (w == 0) {
        float x = (lane < N_BINS) ? sq[lane] : 0.f;
        #pragma unroll
        for (int off = 16; off > 0; off >>= 1)
            x += __shfl_down_sync(0xFFFFFFFFu, x, off);
        if (lane == 0) out[0] = SYNC_COST * (x / (float)N_BINS);
    }
}

// ---------------------------------------------------------------------------
extern "C" void kernel_launch(void* const* d_in, const int* in_sizes, int n_in,
                              void* d_out, int out_size)
{
    const float* spikes    = (const float*)d_in[0];
    const float* exp_fanos = (const float*)d_in[1];
    const int*   trials    = (const int*)  d_in[2];
    const int*   idx       = (const int*)  d_in[3];
    const int*   counts    = (const int*)  d_in[4];
    float*       out       = (float*)d_out;

    trial_map_kernel<<<1, 32>>>(trials);
    sort_prep_kernel<<<N_SAMPLES, SORT_N>>>(idx, counts);

    dim3 g1((T_MS + TB - 1) / TB, N_TRIALS);   // (79, 8)
    sel_kernel<<<g1, 256>>>(spikes, counts);

    dim3 g2(N_SAMPLES, NBGRP);
    fano_kernel<<<g2, 256>>>();

    loss_kernel<<<1, 640>>>(exp_fanos, out);
}

// round 13
// speedup vs baseline: 1.6978x; 1.0526x over previous
#include <cuda_runtime.h>
#include <stdint.h>

#define N_TRIALS   8
#define T_MS       2500
#define N_NEURONS  16000
#define N_SAMPLES  50
#define K_MAX      160
#define N_BINS     20
#define SYNC_COST  10.0f
#define EPS_F      1e-7f
#define SORT_N     256
#define NC         8            // neuron-space chunks (2000 neurons each)
#define MAXS       24           // max samples per trial (headroom over E[6.25])
#define TB         32           // t per block

// round(logspace(-3,0,20)*1000), matching numpy exactly
__constant__ int c_bins[N_BINS] = {1,1,2,3,4,6,9,13,18,26,38,55,78,113,162,234,336,483,695,1000};

// scratch (no allocations allowed -> __device__ globals)
__device__ int   g_sidx[N_SAMPLES * K_MAX];        // per-sample ASCENDING active indices
__device__ int   g_soff[N_SAMPLES * (NC + 1)];     // per-sample chunk offsets into sorted list
__device__ int   g_slist[N_TRIALS * MAXS];         // sample ids per trial
__device__ int   g_scount[N_TRIALS];
__device__ float g_sel[N_SAMPLES * T_MS];
__device__ float g_fano_parts[N_BINS * N_SAMPLES];

// ---------------------------------------------------------------------------
// Kernel 0a: trial -> sample-list map (1 tiny block, deterministic).
// ---------------------------------------------------------------------------
__global__ void trial_map_kernel(const int* __restrict__ trials)
{
    if (threadIdx.x == 0) {
        int cnt[N_TRIALS];
        for (int r = 0; r < N_TRIALS; r++) cnt[r] = 0;
        for (int s = 0; s < N_SAMPLES; s++) {
            const int r = trials[s];
            g_slist[r * MAXS + cnt[r]] = s;
            cnt[r]++;
        }
        for (int r = 0; r < N_TRIALS; r++) g_scount[r] = cnt[r];
    }
}

// ---------------------------------------------------------------------------
// Kernel 0b: per sample, bitonic sort its cnt active indices ascending
// (exact: 0/1 summands are order-independent), then chunk offsets by
// binary search at neuron thresholds c*2000.
// ---------------------------------------------------------------------------
__global__ void __launch_bounds__(SORT_N) sort_prep_kernel(const int* __restrict__ idx,
                                                           const int* __restrict__ counts)
{
    const int s   = blockIdx.x;
    const int tid = threadIdx.x;
    const int cnt = counts[s];

    __shared__ int a[SORT_N];
    a[tid] = (tid < cnt) ? idx[s * K_MAX + tid] : 0x7FFFFFFF;
    __syncthreads();

    for (int k = 2; k <= SORT_N; k <<= 1) {
        for (int j = k >> 1; j > 0; j >>= 1) {
            const int ixj = tid ^ j;
            if (ixj > tid) {
                const bool up = ((tid & k) == 0);
                const int x = a[tid], y = a[ixj];
                if ((x > y) == up) { a[tid] = y; a[ixj] = x; }
            }
            __syncthreads();
        }
    }

    if (tid < K_MAX)
        g_sidx[s * K_MAX + tid] = (tid < cnt) ? a[tid] : 0;

    // chunk offsets: lower_bound(a[0..cnt), c * (N_NEURONS/NC))
    if (tid <= NC) {
        const int thr = tid * (N_NEURONS / NC);
        int lo = 0, hi = cnt;
        while (lo < hi) {
            const int mid = (lo + hi) >> 1;
            if (a[mid] < thr) lo = mid + 1; else hi = mid;
        }
        g_soff[s * (NC + 1) + tid] = lo;
    }
}

// ---------------------------------------------------------------------------
// Kernel 1 (PROVEN WIN — unchanged): sel.
// Block = (trial r, 32 consecutive t) x 8 warp-slots; chunk-lockstep over
// NC neuron windows so all warps share DRAM lines within a window.
// ---------------------------------------------------------------------------
__global__ void __launch_bounds__(256) sel_kernel(const float* __restrict__ spikes,
                                                  const int*   __restrict__ counts)
{
    const int r   = blockIdx.y;
    const int t0  = blockIdx.x * TB;
    const int tid = threadIdx.x;
    const int lane = tid & 31;
    const int w    = tid >> 5;

    __shared__ uint16_t lists[MAXS][K_MAX];   // 7.7 KB
    __shared__ int      soff_s[MAXS][NC + 1];
    __shared__ int      sids[MAXS];
    __shared__ int      sc_s;

    if (tid == 0) sc_s = g_scount[r];
    __syncthreads();
    const int sc = sc_s;
    if (sc == 0) return;

    for (int i = tid; i < sc; i += 256) sids[i] = g_slist[r * MAXS + i];
    __syncthreads();

    for (int p = tid; p < sc * K_MAX; p += 256) {
        const int si = p / K_MAX, k = p % K_MAX;
        lists[si][k] = (uint16_t)g_sidx[sids[si] * K_MAX + k];
    }
    for (int p = tid; p < sc * (NC + 1); p += 256) {
        const int si = p / (NC + 1), c = p % (NC + 1);
        soff_s[si][c] = g_soff[sids[si] * (NC + 1) + c];
    }
    __syncthreads();

    const int  t      = t0 + lane;
    const bool active = (t < T_MS);
    const float* __restrict__ row =
        spikes + ((long long)r * T_MS + t) * (long long)N_NEURONS;

    float acc0 = 0.f, acc1 = 0.f, acc2 = 0.f;

    #pragma unroll 1
    for (int c = 0; c < NC; c++) {
        if (active) {
            {
                const int si = w;
                if (si < sc) {
                    const uint16_t* __restrict__ L = &lists[si][0];
                    int j = soff_s[si][c];
                    const int j1 = soff_s[si][c + 1];
                    float b0=0.f,b1=0.f,b2=0.f,b3=0.f;
                    for (; j + 4 <= j1; j += 4) {
                        b0 += row[L[j+0]]; b1 += row[L[j+1]];
                        b2 += row[L[j+2]]; b3 += row[L[j+3]];
                    }
                    float x = (b0+b1)+(b2+b3);
                    for (; j < j1; j++) x += row[L[j]];
                    acc0 += x;
                }
            }
            {
                const int si = w + 8;
                if (si < sc) {
                    const uint16_t* __restrict__ L = &lists[si][0];
                    int j = soff_s[si][c];
                    const int j1 = soff_s[si][c + 1];
                    float b0=0.f,b1=0.f,b2=0.f,b3=0.f;
                    for (; j + 4 <= j1; j += 4) {
                        b0 += row[L[j+0]]; b1 += row[L[j+1]];
                        b2 += row[L[j+2]]; b3 += row[L[j+3]];
                    }
                    float x = (b0+b1)+(b2+b3);
                    for (; j < j1; j++) x += row[L[j]];
                    acc1 += x;
                }
            }
            {
                const int si = w + 16;
                if (si < sc) {
                    const uint16_t* __restrict__ L = &lists[si][0];
                    int j = soff_s[si][c];
                    const int j1 = soff_s[si][c + 1];
                    float b0=0.f,b1=0.f,b2=0.f,b3=0.f;
                    for (; j + 4 <= j1; j += 4) {
                        b0 += row[L[j+0]]; b1 += row[L[j+1]];
                        b2 += row[L[j+2]]; b3 += row[L[j+3]];
                    }
                    float x = (b0+b1)+(b2+b3);
                    for (; j < j1; j++) x += row[L[j]];
                    acc2 += x;
                }
            }
        }
        __syncthreads();   // lockstep: all warps stay in the same neuron window
    }

    if (active) {
        if (w      < sc) g_sel[sids[w     ] * T_MS + t] = acc0;   // exact ints
        if (w + 8  < sc) g_sel[sids[w + 8 ] * T_MS + t] = acc1;
        if (w + 16 < sc) g_sel[sids[w + 16] * T_MS + t] = acc2;
    }
}

// ---------------------------------------------------------------------------
// Kernel 2 (REWORKED): fano, one WARP per (s, b) pair — no __syncthreads,
// shuffle-only reductions, fully latency-pipelined.
// 1000 warps = 125 blocks x 256 threads.
// Pass 1: total = sum(row[0:nb*bs]) (exact int). mean = total/nb.
// Pass 2: per-lane binsums recomputed, accumulate (binsum-mean)^2.
// ---------------------------------------------------------------------------
__global__ void __launch_bounds__(256) fano_kernel()
{
    const int gw   = (blockIdx.x * 256 + threadIdx.x) >> 5;   // global warp id
    const int lane = threadIdx.x & 31;
    if (gw >= N_SAMPLES * N_BINS) return;

    const int s  = gw / N_BINS;
    const int b  = gw % N_BINS;
    const int bs = c_bins[b];
    const int nb = T_MS / bs;
    const int lim = nb * bs;

    const float* __restrict__ row = g_sel + s * T_MS;

    // pass 1: total sum over [0, nb*bs) — exact integers
    float tot = 0.f;
    for (int i = lane; i < lim; i += 32) tot += row[i];
    #pragma unroll
    for (int o = 16; o > 0; o >>= 1)
        tot += __shfl_xor_sync(0xFFFFFFFFu, tot, o);
    const float mean = tot / (float)nb;          // same in all lanes

    // pass 2: per-lane bins, accumulate squared deviations
    float ssq = 0.f;
    for (int j = lane; j < nb; j += 32) {
        const int base = j * bs;
        float b0=0.f, b1=0.f, b2=0.f, b3=0.f;
        int i = 0;
        for (; i + 4 <= bs; i += 4) {
            b0 += row[base + i + 0];
            b1 += row[base + i + 1];
            b2 += row[base + i + 2];
            b3 += row[base + i + 3];
        }
        float acc = (b0+b1)+(b2+b3);
        for (; i < bs; i++) acc += row[base + i];
        const float d = acc - mean;
        ssq += d * d;
    }
    #pragma unroll
    for (int o = 16; o > 0; o >>= 1)
        ssq += __shfl_xor_sync(0xFFFFFFFFu, ssq, o);

    if (lane == 0) {
        const float var = ssq / (float)nb;
        g_fano_parts[b * N_SAMPLES + s] = var / fmaxf(mean, EPS_F);
    }
}

// ---------------------------------------------------------------------------
// Kernel 3: parallel loss. 20 warps, warp b reduces its 50 sample fanos.
// ---------------------------------------------------------------------------
__global__ void __launch_bounds__(640) loss_kernel(const float* __restrict__ exp_fanos,
                                                   float* __restrict__ out)
{
    const int w    = threadIdx.x >> 5;
    const int lane = threadIdx.x & 31;

    __shared__ float sq[N_BINS];

    float v = 0.f;
    if (lane < N_SAMPLES)      v += g_fano_parts[w * N_SAMPLES + lane];
    if (lane + 32 < N_SAMPLES) v += g_fano_parts[w * N_SAMPLES + lane + 32];
    #pragma unroll
    for (int off = 16; off > 0; off >>= 1)
        v += __shfl_down_sync(0xFFFFFFFFu, v, off);
    if (lane == 0) {
        const float fano = v / (float)N_SAMPLES;
        const float d = exp_fanos[w] - fano;
        sq[w] = d * d;
    }
    __syncthreads();

    if (w == 0) {
        float x = (lane < N_BINS) ? sq[lane] : 0.f;
        #pragma unroll
        for (int off = 16; off > 0; off >>= 1)
            x += __shfl_down_sync(0xFFFFFFFFu, x, off);
        if (lane == 0) out[0] = SYNC_COST * (x / (float)N_BINS);
    }
}

// ---------------------------------------------------------------------------
extern "C" void kernel_launch(void* const* d_in, const int* in_sizes, int n_in,
                              void* d_out, int out_size)
{
    const float* spikes    = (const float*)d_in[0];
    const float* exp_fanos = (const float*)d_in[1];
    const int*   trials    = (const int*)  d_in[2];
    const int*   idx       = (const int*)  d_in[3];
    const int*   counts    = (const int*)  d_in[4];
    float*       out       = (float*)d_out;

    trial_map_kernel<<<1, 32>>>(trials);
    sort_prep_kernel<<<N_SAMPLES, SORT_N>>>(idx, counts);

    dim3 g1((T_MS + TB - 1) / TB, N_TRIALS);   // (79, 8)
    sel_kernel<<<g1, 256>>>(spikes, counts);

    const int fano_warps  = N_SAMPLES * N_BINS;            // 1000
    const int fano_blocks = (fano_warps * 32 + 255) / 256; // 125
    fano_kernel<<<fano_blocks, 256>>>();

    loss_kernel<<<1, 640>>>(exp_fanos, out);
}

// round 16
// speedup vs baseline: 1.7694x; 1.0422x over previous
#include <cuda_runtime.h>
#include <stdint.h>

#define N_TRIALS   8
#define T_MS       2500
#define N_NEURONS  16000
#define N_SAMPLES  50
#define K_MAX      160
#define N_BINS     20
#define SYNC_COST  10.0f
#define EPS_F      1e-7f
#define SORT_N     256
#define NC         8            // neuron-space chunks (2000 neurons each)
#define MAXS       24           // max samples per trial (headroom over E[6.25])
#define TB         32           // t per block

// round(logspace(-3,0,20)*1000), matching numpy exactly
__constant__ int c_bins[N_BINS] = {1,1,2,3,4,6,9,13,18,26,38,55,78,113,162,234,336,483,695,1000};

// scratch (no allocations allowed -> __device__ globals)
__device__ int   g_sidx[N_SAMPLES * K_MAX];        // per-sample ASCENDING active indices
__device__ int   g_soff[N_SAMPLES * (NC + 1)];     // per-sample chunk offsets into sorted list
__device__ float g_sel[N_SAMPLES * T_MS];
__device__ float g_fano_parts[N_BINS * N_SAMPLES];

// ---------------------------------------------------------------------------
// Kernel 0: per sample, bitonic sort its cnt active indices ascending
// (exact: 0/1 summands are order-independent), then chunk offsets by
// binary search at neuron thresholds c*2000.
// ---------------------------------------------------------------------------
__global__ void __launch_bounds__(SORT_N) sort_prep_kernel(const int* __restrict__ idx,
                                                           const int* __restrict__ counts)
{
    const int s   = blockIdx.x;
    const int tid = threadIdx.x;
    const int cnt = counts[s];

    __shared__ int a[SORT_N];
    a[tid] = (tid < cnt) ? idx[s * K_MAX + tid] : 0x7FFFFFFF;
    __syncthreads();

    for (int k = 2; k <= SORT_N; k <<= 1) {
        for (int j = k >> 1; j > 0; j >>= 1) {
            const int ixj = tid ^ j;
            if (ixj > tid) {
                const bool up = ((tid & k) == 0);
                const int x = a[tid], y = a[ixj];
                if ((x > y) == up) { a[tid] = y; a[ixj] = x; }
            }
            __syncthreads();
        }
    }

    if (tid < K_MAX)
        g_sidx[s * K_MAX + tid] = (tid < cnt) ? a[tid] : 0;

    // chunk offsets: lower_bound(a[0..cnt), c * (N_NEURONS/NC))
    if (tid <= NC) {
        const int thr = tid * (N_NEURONS / NC);
        int lo = 0, hi = cnt;
        while (lo < hi) {
            const int mid = (lo + hi) >> 1;
            if (a[mid] < thr) lo = mid + 1; else hi = mid;
        }
        g_soff[s * (NC + 1) + tid] = lo;
    }
}

// ---------------------------------------------------------------------------
// Kernel 1 (PROVEN WIN — hot loop unchanged): sel.
// Block = (trial r, 32 consecutive t) x 8 warp-slots; chunk-lockstep over
// NC neuron windows so all warps share DRAM lines within a window.
// Trial->sample map now built in-block from trials[] (removes a kernel).
// ---------------------------------------------------------------------------
__global__ void __launch_bounds__(256) sel_kernel(const float* __restrict__ spikes,
                                                  const int*   __restrict__ trials,
                                                  const int*   __restrict__ counts)
{
    const int r   = blockIdx.y;
    const int t0  = blockIdx.x * TB;
    const int tid = threadIdx.x;
    const int lane = tid & 31;
    const int w    = tid >> 5;

    __shared__ uint16_t lists[MAXS][K_MAX];   // 7.7 KB
    __shared__ int      soff_s[MAXS][NC + 1];
    __shared__ int      sids[MAXS];
    __shared__ int      sc_s;

    if (tid == 0) {
        int c = 0;
        for (int s = 0; s < N_SAMPLES; s++)
            if (trials[s] == r && c < MAXS) sids[c++] = s;
        sc_s = c;
    }
    __syncthreads();
    const int sc = sc_s;
    if (sc == 0) return;

    for (int p = tid; p < sc * K_MAX; p += 256) {
        const int si = p / K_MAX, k = p % K_MAX;
        lists[si][k] = (uint16_t)g_sidx[sids[si] * K_MAX + k];
    }
    for (int p = tid; p < sc * (NC + 1); p += 256) {
        const int si = p / (NC + 1), c = p % (NC + 1);
        soff_s[si][c] = g_soff[sids[si] * (NC + 1) + c];
    }
    __syncthreads();

    const int  t      = t0 + lane;
    const bool active = (t < T_MS);
    const float* __restrict__ row =
        spikes + ((long long)r * T_MS + t) * (long long)N_NEURONS;

    float acc0 = 0.f, acc1 = 0.f, acc2 = 0.f;

    #pragma unroll 1
    for (int c = 0; c < NC; c++) {
        if (active) {
            {
                const int si = w;
                if (si < sc) {
                    const uint16_t* __restrict__ L = &lists[si][0];
                    int j = soff_s[si][c];
                    const int j1 = soff_s[si][c + 1];
                    float b0=0.f,b1=0.f,b2=0.f,b3=0.f;
                    for (; j + 4 <= j1; j += 4) {
                        b0 += row[L[j+0]]; b1 += row[L[j+1]];
                        b2 += row[L[j+2]]; b3 += row[L[j+3]];
                    }
                    float x = (b0+b1)+(b2+b3);
                    for (; j < j1; j++) x += row[L[j]];
                    acc0 += x;
                }
            }
            {
                const int si = w + 8;
                if (si < sc) {
                    const uint16_t* __restrict__ L = &lists[si][0];
                    int j = soff_s[si][c];
                    const int j1 = soff_s[si][c + 1];
                    float b0=0.f,b1=0.f,b2=0.f,b3=0.f;
                    for (; j + 4 <= j1; j += 4) {
                        b0 += row[L[j+0]]; b1 += row[L[j+1]];
                        b2 += row[L[j+2]]; b3 += row[L[j+3]];
                    }
                    float x = (b0+b1)+(b2+b3);
                    for (; j < j1; j++) x += row[L[j]];
                    acc1 += x;
                }
            }
            {
                const int si = w + 16;
                if (si < sc) {
                    const uint16_t* __restrict__ L = &lists[si][0];
                    int j = soff_s[si][c];
                    const int j1 = soff_s[si][c + 1];
                    float b0=0.f,b1=0.f,b2=0.f,b3=0.f;
                    for (; j + 4 <= j1; j += 4) {
                        b0 += row[L[j+0]]; b1 += row[L[j+1]];
                        b2 += row[L[j+2]]; b3 += row[L[j+3]];
                    }
                    float x = (b0+b1)+(b2+b3);
                    for (; j < j1; j++) x += row[L[j]];
                    acc2 += x;
                }
            }
        }
        __syncthreads();   // lockstep: all warps stay in the same neuron window
    }

    if (active) {
        if (w      < sc) g_sel[sids[w     ] * T_MS + t] = acc0;   // exact ints
        if (w + 8  < sc) g_sel[sids[w + 8 ] * T_MS + t] = acc1;
        if (w + 16 < sc) g_sel[sids[w + 16] * T_MS + t] = acc2;
    }
}

// ---------------------------------------------------------------------------
// Kernel 2 (REWORKED): fano, one BLOCK per sample (640 thr = 20 warps).
// Row staged to smem once (single barrier), then warp b computes bin b
// independently from smem — no further barriers, smem-latency loads.
// Arithmetic lane-for-lane identical to warp-per-(s,b) version.
// ---------------------------------------------------------------------------
__global__ void __launch_bounds__(640) fano_kernel()
{
    const int s    = blockIdx.x;
    const int tid  = threadIdx.x;
    const int b    = tid >> 5;       // warp id = bin
    const int lane = tid & 31;

    __shared__ float row[T_MS];      // 10 KB

    const float* __restrict__ grow = g_sel + s * T_MS;
    for (int t = tid; t < T_MS; t += 640)
        row[t] = grow[t];
    __syncthreads();

    const int bs  = c_bins[b];
    const int nb  = T_MS / bs;
    const int lim = nb * bs;

    // pass 1: total sum over [0, nb*bs) — exact integers
    float tot = 0.f;
    for (int i = lane; i < lim; i += 32) tot += row[i];
    #pragma unroll
    for (int o = 16; o > 0; o >>= 1)
        tot += __shfl_xor_sync(0xFFFFFFFFu, tot, o);
    const float mean = tot / (float)nb;          // same in all lanes

    // pass 2: per-lane bins, accumulate squared deviations
    float ssq = 0.f;
    for (int j = lane; j < nb; j += 32) {
        const int base = j * bs;
        float b0=0.f, b1=0.f, b2=0.f, b3=0.f;
        int i = 0;
        for (; i + 4 <= bs; i += 4) {
            b0 += row[base + i + 0];
            b1 += row[base + i + 1];
            b2 += row[base + i + 2];
            b3 += row[base + i + 3];
        }
        float acc = (b0+b1)+(b2+b3);
        for (; i < bs; i++) acc += row[base + i];
        const float d = acc - mean;
        ssq += d * d;
    }
    #pragma unroll
    for (int o = 16; o > 0; o >>= 1)
        ssq += __shfl_xor_sync(0xFFFFFFFFu, ssq, o);

    if (lane == 0) {
        const float var = ssq / (float)nb;
        g_fano_parts[b * N_SAMPLES + s] = var / fmaxf(mean, EPS_F);
    }
}

// ---------------------------------------------------------------------------
// Kernel 3: parallel loss. 20 warps, warp b reduces its 50 sample fanos.
// ---------------------------------------------------------------------------
__global__ void __launch_bounds__(640) loss_kernel(const float* __restrict__ exp_fanos,
                                                   float* __restrict__ out)
{
    const int w    = threadIdx.x >> 5;
    const int lane = threadIdx.x & 31;

    __shared__ float sq[N_BINS];

    float v = 0.f;
    if (lane < N_SAMPLES)      v += g_fano_parts[w * N_SAMPLES + lane];
    if (lane + 32 < N_SAMPLES) v += g_fano_parts[w * N_SAMPLES + lane + 32];
    #pragma unroll
    for (int off = 16; off > 0; off >>= 1)
        v += __shfl_down_sync(0xFFFFFFFFu, v, off);
    if (lane == 0) {
        const float fano = v / (float)N_SAMPLES;
        const float d = exp_fanos[w] - fano;
        sq[w] = d * d;
    }
    __syncthreads();

    if (w == 0) {
        float x = (lane < N_BINS) ? sq[lane] : 0.f;
        #pragma unroll
        for (int off = 16; off > 0; off >>= 1)
            x += __shfl_down_sync(0xFFFFFFFFu, x, off);
        if (lane == 0) out[0] = SYNC_COST * (x / (float)N_BINS);
    }
}

// ---------------------------------------------------------------------------
extern "C" void kernel_launch(void* const* d_in, const int* in_sizes, int n_in,
                              void* d_out, int out_size)
{
    const float* spikes    = (const float*)d_in[0];
    const float* exp_fanos = (const float*)d_in[1];
    const int*   trials    = (const int*)  d_in[2];
    const int*   idx       = (const int*)  d_in[3];
    const int*   counts    = (const int*)  d_in[4];
    float*       out       = (float*)d_out;

    sort_prep_kernel<<<N_SAMPLES, SORT_N>>>(idx, counts);

    dim3 g1((T_MS + TB - 1) / TB, N_TRIALS);   // (79, 8)
    sel_kernel<<<g1, 256>>>(spikes, trials, counts);

    fano_kernel<<<N_SAMPLES, 640>>>();

    loss_kernel<<<1, 640>>>(exp_fanos, out);
}